// round 12
// baseline (speedup 1.0000x reference)
#include <cuda_runtime.h>
#include <math.h>

#define N_NODES 100000
#define N_EDGES 1250000
#define G_GRAPHS 256
#define IN_DIM 8
#define DIM 64
#define EPS 1e-5f
#define NB1 ((N_NODES + 255) / 256)   // 391 scan blocks

typedef unsigned long long ull;

#define FFMA2(d, a, b, c) \
    asm("fma.rn.f32x2 %0, %1, %2, %3;" : "=l"(d) : "l"(a), "l"(b), "l"(c))
#define DUP2(d, x) \
    asm("mov.b64 %0, {%1, %1};" : "=l"(d) : "r"(__float_as_uint(x)))

// ---------------- scratch (device globals; no allocation allowed) ----------
__device__ float g_deg[N_NODES];
__device__ float g_dinv[N_NODES];
__device__ int   g_cnt[N_NODES];
__device__ int   g_fill[N_NODES];
__device__ int   g_rows[N_NODES];
__device__ int   g_bsum[NB1];
__device__ int   g_rowstart[N_NODES];
__device__ __align__(16) int2  g_csr[N_EDGES];       // {src, raw w bits}
__device__ __align__(16) float g_xs[N_NODES * IN_DIM]; // dinv[n]*x[n]
__device__ __align__(16) float g_t[N_NODES * DIM];   // post-activation (pre-BN)
__device__ __align__(16) float g_h[N_NODES * DIM];   // h' = dinv[n] * z[n]
__device__ __align__(16) float g_stats[3 * 2 * DIM]; // per-layer [sum64|sumsq64]

// ---------------- init ----------------
__global__ void init_kernel() {
    int i = blockIdx.x * blockDim.x + threadIdx.x;
    if (i < N_NODES) { g_deg[i] = 1.0f; g_cnt[i] = 0; g_fill[i] = 0; }
    if (blockIdx.x == 0) {
        for (int k = threadIdx.x; k < 3 * 2 * DIM; k += 256) g_stats[k] = 0.0f;
    }
}

// 2 edges per thread: int2 dst + float4 attrs
__global__ void count_kernel(const int* __restrict__ ei,
                             const float* __restrict__ ea) {
    int i = blockIdx.x * blockDim.x + threadIdx.x;
    if (i < N_EDGES / 2) {
        int2 d = *reinterpret_cast<const int2*>(ei + N_EDGES + 2 * i);
        float4 wv = *reinterpret_cast<const float4*>(ea + 4 * i);
        atomicAdd(&g_cnt[d.x], 1);
        atomicAdd(&g_deg[d.x], wv.y);
        atomicAdd(&g_cnt[d.y], 1);
        atomicAdd(&g_deg[d.y], wv.w);
    }
}

// block-local exclusive scan + block totals + dinv + xs prescale fused
__global__ void scan1_kernel(const float* __restrict__ x) {
    __shared__ int sdata[256];
    int t = threadIdx.x;
    int n = blockIdx.x * 256 + t;
    int v = (n < N_NODES) ? g_cnt[n] : 0;
    int val = v;
    sdata[t] = val;
    __syncthreads();
    for (int off = 1; off < 256; off <<= 1) {
        int y = (t >= off) ? sdata[t - off] : 0;
        __syncthreads();
        val += y;
        sdata[t] = val;
        __syncthreads();
    }
    if (n < N_NODES) {
        g_rows[n] = val - v;
        float d = g_deg[n];
        float di = (d > 0.0f) ? rsqrtf(d) : 0.0f;
        g_dinv[n] = di;
        float4 xa = reinterpret_cast<const float4*>(x)[n * 2];
        float4 xb = reinterpret_cast<const float4*>(x)[n * 2 + 1];
        xa.x *= di; xa.y *= di; xa.z *= di; xa.w *= di;
        xb.x *= di; xb.y *= di; xb.z *= di; xb.w *= di;
        reinterpret_cast<float4*>(g_xs)[n * 2] = xa;
        reinterpret_cast<float4*>(g_xs)[n * 2 + 1] = xb;
    }
    if (t == 255) g_bsum[blockIdx.x] = val;
}

// each block redundantly computes its bsum prefix, writes final rowstart
__global__ void scan23_kernel() {
    __shared__ int sdata[512];
    __shared__ int rs[256];
    int t = threadIdx.x;
    sdata[t] = (t < NB1) ? g_bsum[t] : 0;
    sdata[t + 256] = (t + 256 < NB1) ? g_bsum[t + 256] : 0;
    __syncthreads();
    int b = blockIdx.x;
    int part = 0;
    if (t < b) part += sdata[t];
    if (t + 256 < b) part += sdata[t + 256];
    rs[t] = part;
    __syncthreads();
    for (int off = 128; off > 0; off >>= 1) {
        if (t < off) rs[t] += rs[t + off];
        __syncthreads();
    }
    int off0 = rs[0];
    int n = b * 256 + t;
    if (n < N_NODES) g_rowstart[n] = g_rows[n] + off0;
}

// 2 edges per thread; store RAW w (dinv folded into h'/xs)
__global__ void fill_kernel(const int* __restrict__ ei,
                            const float* __restrict__ ea) {
    int i = blockIdx.x * blockDim.x + threadIdx.x;
    if (i < N_EDGES / 2) {
        int2 s = *reinterpret_cast<const int2*>(ei + 2 * i);
        int2 d = *reinterpret_cast<const int2*>(ei + N_EDGES + 2 * i);
        float4 wv = *reinterpret_cast<const float4*>(ea + 4 * i);
        int p0 = g_rowstart[d.x] + atomicAdd(&g_fill[d.x], 1);
        g_csr[p0] = make_int2(s.x, __float_as_int(wv.y));
        int p1 = g_rowstart[d.y] + atomicAdd(&g_fill[d.y], 1);
        g_csr[p1] = make_int2(s.y, __float_as_int(wv.w));
    }
}

// ---------------- layer 0 fused: gather xs + gemm0 + relu + stats ----------
// 32 nodes per block (exact: 100000 = 3125*32), 256 threads
__global__ void __launch_bounds__(256) l0_kernel(const float* __restrict__ W0,
                                                 const float* __restrict__ b0) {
    __shared__ float sA[32][IN_DIM];
    __shared__ float sW[IN_DIM][DIM];
    __shared__ float red[4][DIM], red2[4][DIM];
    int tid = threadIdx.x;
    int w = tid >> 5, l = tid & 31;
    int sub = l >> 3, j8 = l & 7;
    for (int i = tid; i < IN_DIM * DIM; i += 256)
        sW[i >> 6][i & 63] = W0[i];
    int nbase = blockIdx.x * 32;
    for (int t = 0; t < 4; t++) {
        int ln = w * 4 + t;
        int n = nbase + ln;
        int start = g_rowstart[n];
        int end = start + g_cnt[n];
        float acc = 0.0f;
        for (int e = start + sub; e < end; e += 4) {
            int2 c = g_csr[e];
            acc += __int_as_float(c.y) * g_xs[(size_t)c.x * IN_DIM + j8];
        }
        acc += __shfl_xor_sync(0xffffffffu, acc, 8);
        acc += __shfl_xor_sync(0xffffffffu, acc, 16);
        float di = g_dinv[n];
        if (l < 8) sA[ln][l] = di * (acc + g_xs[(size_t)n * IN_DIM + l]);
    }
    __syncthreads();
    int j = tid & 63, grp = tid >> 6;
    float bj = b0[j];
    float s = 0.0f, s2 = 0.0f;
    for (int i = 0; i < 8; i++) {
        int ln = grp * 8 + i;
        float acc = bj;
#pragma unroll
        for (int k = 0; k < IN_DIM; k++) acc += sA[ln][k] * sW[k][j];
        float r = fmaxf(acc, 0.0f);
        g_t[(size_t)(nbase + ln) * DIM + j] = r;
        s += r;
        s2 += r * r;
    }
    red[grp][j] = s;
    red2[grp][j] = s2;
    __syncthreads();
    if (tid < 64) {
        atomicAdd(&g_stats[tid], red[0][tid] + red[1][tid] + red[2][tid] + red[3][tid]);
    } else if (tid < 128) {
        int jj = tid - 64;
        atomicAdd(&g_stats[64 + jj],
                  red2[0][jj] + red2[1][jj] + red2[2][jj] + red2[3][jj]);
    }
}

// ---------------- dense layers ----------------
// h'[n,j] = dinv[n] * sum_k (A[k]*t[n,k]+B[k]) * W[k,j] ; packed f32x2 FMA
__global__ void __launch_bounds__(256) gemm64_kernel(const float* __restrict__ W,
                                                     const float* __restrict__ gamma,
                                                     const float* __restrict__ beta,
                                                     int soff) {
    __shared__ float sW[DIM][DIM];
    __shared__ float sH[DIM][DIM];
    __shared__ float sAf[DIM], sBf[DIM];
    int tid = threadIdx.x;           // 256 threads
    int n_base = blockIdx.x * 64;
    if (tid < 64) {
        float mu = g_stats[soff + tid] * (1.0f / N_NODES);
        float var = g_stats[soff + 64 + tid] * (1.0f / N_NODES) - mu * mu;
        float inv = rsqrtf(var + EPS);
        float A = gamma[tid] * inv;
        sAf[tid] = A;
        sBf[tid] = beta[tid] - mu * A;
    }
    for (int i = tid; i < 1024; i += 256)
        reinterpret_cast<float4*>(&sW[0][0])[i] =
            reinterpret_cast<const float4*>(W)[i];
    __syncthreads();
    for (int i = tid; i < 1024; i += 256) {
        int n = i >> 4;
        int k4 = (i & 15) << 2;
        float4 v = make_float4(0.f, 0.f, 0.f, 0.f);
        int row = n_base + n;
        if (row < N_NODES)
            v = reinterpret_cast<const float4*>(g_t + (size_t)row * DIM)[i & 15];
        float4 A = *reinterpret_cast<const float4*>(sAf + k4);
        float4 B = *reinterpret_cast<const float4*>(sBf + k4);
        sH[k4 + 0][n] = A.x * v.x + B.x;
        sH[k4 + 1][n] = A.y * v.y + B.y;
        sH[k4 + 2][n] = A.z * v.z + B.z;
        sH[k4 + 3][n] = A.w * v.w + B.w;
    }
    __syncthreads();
    int tx = tid & 15, ty = tid >> 4;
    int j0 = tx * 4, n0 = ty * 4;
    ull acc[4][2];
#pragma unroll
    for (int r = 0; r < 4; r++) { acc[r][0] = 0ull; acc[r][1] = 0ull; }
#pragma unroll
    for (int k = 0; k < DIM; k++) {
        ulonglong2 wv = *reinterpret_cast<const ulonglong2*>(&sW[k][j0]);
        float4 hv = *reinterpret_cast<const float4*>(&sH[k][n0]);
        ull h0, h1, h2, h3;
        DUP2(h0, hv.x); DUP2(h1, hv.y); DUP2(h2, hv.z); DUP2(h3, hv.w);
        FFMA2(acc[0][0], h0, wv.x, acc[0][0]);
        FFMA2(acc[0][1], h0, wv.y, acc[0][1]);
        FFMA2(acc[1][0], h1, wv.x, acc[1][0]);
        FFMA2(acc[1][1], h1, wv.y, acc[1][1]);
        FFMA2(acc[2][0], h2, wv.x, acc[2][0]);
        FFMA2(acc[2][1], h2, wv.y, acc[2][1]);
        FFMA2(acc[3][0], h3, wv.x, acc[3][0]);
        FFMA2(acc[3][1], h3, wv.y, acc[3][1]);
    }
#pragma unroll
    for (int r = 0; r < 4; r++) {
        int row = n_base + n0 + r;
        if (row < N_NODES) {
            float di = g_dinv[row];
            float4 o;
            o.x = di * __uint_as_float((unsigned)(acc[r][0] & 0xffffffffull));
            o.y = di * __uint_as_float((unsigned)(acc[r][0] >> 32));
            o.z = di * __uint_as_float((unsigned)(acc[r][1] & 0xffffffffull));
            o.w = di * __uint_as_float((unsigned)(acc[r][1] >> 32));
            *reinterpret_cast<float4*>(g_h + (size_t)row * DIM + j0) = o;
        }
    }
}

// gather (raw w over h') + self + bias + relu + stats.
// warp per node (4 sequential); half-warps process even/odd edges with float4.
__global__ void __launch_bounds__(256) gather64_kernel(const float* __restrict__ bias,
                                                       int soff) {
    int tid = threadIdx.x;
    int w = tid >> 5, l = tid & 31;
    int hw = l >> 4, l16 = l & 15;
    float4 b4 = reinterpret_cast<const float4*>(bias)[l16];
    float4 sacc = make_float4(0.f, 0.f, 0.f, 0.f);
    float4 qacc = make_float4(0.f, 0.f, 0.f, 0.f);
    int nbase = blockIdx.x * 32 + w * 4;
    __shared__ float ss[8][DIM], sq[8][DIM];
    for (int t = 0; t < 4; t++) {
        int n = nbase + t;
        int start = g_rowstart[n];
        int end = start + g_cnt[n];
        float4 acc = make_float4(0.f, 0.f, 0.f, 0.f);
        int e = start;
        for (; e + 4 <= end; e += 4) {
            int2 ca = g_csr[e + hw];
            int2 cb = g_csr[e + 2 + hw];
            float4 ha = *reinterpret_cast<const float4*>(g_h + (size_t)ca.x * DIM + 4 * l16);
            float4 hb = *reinterpret_cast<const float4*>(g_h + (size_t)cb.x * DIM + 4 * l16);
            float va = __int_as_float(ca.y), vb = __int_as_float(cb.y);
            acc.x += va * ha.x + vb * hb.x;
            acc.y += va * ha.y + vb * hb.y;
            acc.z += va * ha.z + vb * hb.z;
            acc.w += va * ha.w + vb * hb.w;
        }
        if (e + 2 <= end) {
            int2 c = g_csr[e + hw];
            float4 h = *reinterpret_cast<const float4*>(g_h + (size_t)c.x * DIM + 4 * l16);
            float v = __int_as_float(c.y);
            acc.x += v * h.x; acc.y += v * h.y;
            acc.z += v * h.z; acc.w += v * h.w;
            e += 2;
        }
        if (e < end && hw == 0) {
            int2 c = g_csr[e];
            float4 h = *reinterpret_cast<const float4*>(g_h + (size_t)c.x * DIM + 4 * l16);
            float v = __int_as_float(c.y);
            acc.x += v * h.x; acc.y += v * h.y;
            acc.z += v * h.z; acc.w += v * h.w;
        }
        acc.x += __shfl_down_sync(0xffffffffu, acc.x, 16);
        acc.y += __shfl_down_sync(0xffffffffu, acc.y, 16);
        acc.z += __shfl_down_sync(0xffffffffu, acc.z, 16);
        acc.w += __shfl_down_sync(0xffffffffu, acc.w, 16);
        if (hw == 0) {
            float di = g_dinv[n];
            float4 self = *reinterpret_cast<const float4*>(g_h + (size_t)n * DIM + 4 * l16);
            float4 r;
            r.x = fmaxf(di * (acc.x + self.x) + b4.x, 0.f);
            r.y = fmaxf(di * (acc.y + self.y) + b4.y, 0.f);
            r.z = fmaxf(di * (acc.z + self.z) + b4.z, 0.f);
            r.w = fmaxf(di * (acc.w + self.w) + b4.w, 0.f);
            *reinterpret_cast<float4*>(g_t + (size_t)n * DIM + 4 * l16) = r;
            sacc.x += r.x; sacc.y += r.y; sacc.z += r.z; sacc.w += r.w;
            qacc.x += r.x * r.x; qacc.y += r.y * r.y;
            qacc.z += r.z * r.z; qacc.w += r.w * r.w;
        }
    }
    if (hw == 0) {
        *reinterpret_cast<float4*>(&ss[w][4 * l16]) = sacc;
        *reinterpret_cast<float4*>(&sq[w][4 * l16]) = qacc;
    }
    __syncthreads();
    if (tid < 64) {
        float s = 0.f;
#pragma unroll
        for (int i = 0; i < 8; i++) s += ss[i][tid];
        atomicAdd(&g_stats[soff + tid], s);
    } else if (tid < 128) {
        int jj = tid - 64;
        float s = 0.f;
#pragma unroll
        for (int i = 0; i < 8; i++) s += sq[i][jj];
        atomicAdd(&g_stats[soff + 64 + jj], s);
    }
}

// ---------------- pooling (final BN affine) + MLP head fused ----------------
__global__ void poolmlp_kernel(const int* __restrict__ batch,
                               const float* __restrict__ gamma,
                               const float* __restrict__ beta,
                               const float* __restrict__ lin1_w,
                               const float* __restrict__ lin1_b,
                               const float* __restrict__ lin2_w,
                               const float* __restrict__ lin2_b,
                               float* __restrict__ out) {
    int g = blockIdx.x;
    int j = threadIdx.x;   // 0..63
    int ty = threadIdx.y;  // 0..3
    int lo = 0, hi = N_NODES;
    while (lo < hi) { int m = (lo + hi) >> 1; if (batch[m] < g) lo = m + 1; else hi = m; }
    int start = lo;
    lo = start; hi = N_NODES;
    while (lo < hi) { int m = (lo + hi) >> 1; if (batch[m] < g + 1) lo = m + 1; else hi = m; }
    int end = lo;
    float acc = 0.0f;
    for (int i = start + ty; i < end; i += 4) acc += g_t[(size_t)i * DIM + j];
    __shared__ float sh4[4][DIM];
    __shared__ float sp[DIM];
    __shared__ float sh[DIM];
    sh4[ty][j] = acc;
    __syncthreads();
    if (ty == 0) {
        float s = sh4[0][j] + sh4[1][j] + sh4[2][j] + sh4[3][j];
        float mu = g_stats[256 + j] * (1.0f / N_NODES);
        float var = g_stats[256 + 64 + j] * (1.0f / N_NODES) - mu * mu;
        float inv = rsqrtf(var + EPS);
        float A = gamma[j] * inv;
        float B = beta[j] - mu * A;
        sp[j] = A * s + B * (float)(end - start);
    }
    __syncthreads();
    float a1 = 0.0f;
#pragma unroll
    for (int k = ty * 16; k < ty * 16 + 16; k++) a1 += sp[k] * lin1_w[k * DIM + j];
    sh4[ty][j] = a1;
    __syncthreads();
    if (ty == 0)
        sh[j] = fmaxf(sh4[0][j] + sh4[1][j] + sh4[2][j] + sh4[3][j] + lin1_b[j], 0.0f);
    __syncthreads();
    if (j == 0 && ty == 0) {
        float o0 = lin2_b[0], o1 = lin2_b[1];
#pragma unroll
        for (int k = 0; k < DIM; k++) {
            o0 += sh[k] * lin2_w[k * 2 + 0];
            o1 += sh[k] * lin2_w[k * 2 + 1];
        }
        float m = fmaxf(o0, o1);
        float lse = m + logf(expf(o0 - m) + expf(o1 - m));
        out[g * 2 + 0] = o0 - lse;
        out[g * 2 + 1] = o1 - lse;
    }
}

// ---------------- launch ----------------
extern "C" void kernel_launch(void* const* d_in, const int* in_sizes, int n_in,
                              void* d_out, int out_size) {
    const float* x        = (const float*)d_in[0];
    const int*   ei       = (const int*)d_in[1];
    const int*   batch    = (const int*)d_in[2];
    const float* ea       = (const float*)d_in[3];
    const float* W0       = (const float*)d_in[4];
    const float* b0       = (const float*)d_in[5];
    const float* Ws       = (const float*)d_in[6];
    const float* bs       = (const float*)d_in[7];
    const float* gammas   = (const float*)d_in[8];
    const float* betas    = (const float*)d_in[9];
    const float* lin1_w   = (const float*)d_in[10];
    const float* lin1_b   = (const float*)d_in[11];
    const float* lin2_w   = (const float*)d_in[12];
    const float* lin2_b   = (const float*)d_in[13];
    float* out = (float*)d_out;

    const int TB = 256;
    const int EB2 = (N_EDGES / 2 + TB - 1) / TB;

    // CSR build + normalization (+ xs prescale)
    init_kernel<<<NB1, TB>>>();
    count_kernel<<<EB2, TB>>>(ei, ea);
    scan1_kernel<<<NB1, TB>>>(x);
    scan23_kernel<<<NB1, TB>>>();
    fill_kernel<<<EB2, TB>>>(ei, ea);

    // layer 0 fused (stats -> slot 0)
    l0_kernel<<<N_NODES / 32, TB>>>(W0, b0);

    // layers 1, 2
    for (int l = 0; l < 2; l++) {
        gemm64_kernel<<<(N_NODES + 63) / 64, 256>>>(
            Ws + (size_t)l * DIM * DIM, gammas + (size_t)l * DIM,
            betas + (size_t)l * DIM, l * 128);
        gather64_kernel<<<N_NODES / 32, 256>>>(bs + (size_t)l * DIM, (l + 1) * 128);
    }

    // pooling (BN slot 2 fused) + head
    poolmlp_kernel<<<G_GRAPHS, dim3(64, 4)>>>(batch, gammas + 2 * DIM, betas + 2 * DIM,
                                              lin1_w, lin1_b, lin2_w, lin2_b, out);
}